// round 15
// baseline (speedup 1.0000x reference)
#include <cuda_runtime.h>
#include <cuda_bf16.h>
#include <cuda_fp16.h>
#include <math.h>
#include <stdint.h>

#define BB 4
#define TT 2048
#define DIMD 1024
#define HH 16
#define DHD 64
#define NQKV 3072
#define KDIM 1024
#define ROWPAD 40   /* gemm smem row pad (fp16): 32 data + 8 pad, 80B stride */
#define APAD 72     /* attention smem row pad (fp16): 64 data + 8 pad, 144B stride */
#define EXP_C 0.045084439f  /* (1/32) * log2(e) */

// ---------------------------------------------------------------------------
// Device-global scratch (all fp16)
// ---------------------------------------------------------------------------
__device__ __half g_q16[BB * HH * TT * DHD];   // [b,h,t,d]
__device__ __half g_k16[BB * HH * TT * DHD];
__device__ __half g_v16[BB * HH * TT * DHD];

__device__ __half g_x16[BB * TT * DIMD];
__device__ __half g_wq16[NQKV * DIMD];
__device__ __half g_wo16[DIMD * DIMD];
__device__ __half g_ao16[BB * TT * DIMD];      // attention out, [b,t,(h d)]

// ---------------------------------------------------------------------------
// Standard-PTX helpers (compute_103-safe)
// ---------------------------------------------------------------------------
__device__ __forceinline__ uint32_t smem_u32(const void* p) {
    uint32_t a;
    asm("{ .reg .u64 t; cvta.to.shared.u64 t, %1; cvt.u32.u64 %0, t; }" : "=r"(a) : "l"(p));
    return a;
}
__device__ __forceinline__ void cp16(uint32_t dst, const void* src) {
    asm volatile("cp.async.cg.shared.global [%0], [%1], 16;" :: "r"(dst), "l"(src));
}
#define CP_COMMIT() asm volatile("cp.async.commit_group;" ::: "memory")
#define CP_WAIT0()  asm volatile("cp.async.wait_group 0;" ::: "memory")
#define CP_WAIT1()  asm volatile("cp.async.wait_group 1;" ::: "memory")
#define CP_WAIT2()  asm volatile("cp.async.wait_group 2;" ::: "memory")

// Taper the wait so stage s's group is complete: rem = remaining stages after s.
__device__ __forceinline__ void cp_wait_taper(int rem) {
    if (rem >= 2)      { CP_WAIT2(); }
    else if (rem == 1) { CP_WAIT1(); }
    else               { CP_WAIT0(); }
}

__device__ __forceinline__ void ldm_x4(uint32_t* r, uint32_t addr) {
    asm volatile("ldmatrix.sync.aligned.m8n8.x4.shared.b16 {%0,%1,%2,%3}, [%4];"
                 : "=r"(r[0]), "=r"(r[1]), "=r"(r[2]), "=r"(r[3]) : "r"(addr));
}
__device__ __forceinline__ void ldm_x4_trans(uint32_t* r, uint32_t addr) {
    asm volatile("ldmatrix.sync.aligned.m8n8.x4.trans.shared.b16 {%0,%1,%2,%3}, [%4];"
                 : "=r"(r[0]), "=r"(r[1]), "=r"(r[2]), "=r"(r[3]) : "r"(addr));
}
__device__ __forceinline__ void mma16816h(float* d, const uint32_t* a, const uint32_t* b) {
    asm volatile(
        "mma.sync.aligned.m16n8k16.row.col.f32.f16.f16.f32 "
        "{%0,%1,%2,%3}, {%4,%5,%6,%7}, {%8,%9}, {%0,%1,%2,%3};"
        : "+f"(d[0]), "+f"(d[1]), "+f"(d[2]), "+f"(d[3])
        : "r"(a[0]), "r"(a[1]), "r"(a[2]), "r"(a[3]), "r"(b[0]), "r"(b[1]));
}
__device__ __forceinline__ uint32_t pack_f16x2(float lo, float hi) {
    uint32_t r;
    asm("cvt.rn.f16x2.f32 %0, %1, %2;" : "=r"(r) : "f"(hi), "f"(lo));
    return r;
}
__device__ __forceinline__ float fexp2(float x) {
    float r;
    asm("ex2.approx.ftz.f32 %0, %1;" : "=f"(r) : "f"(x));
    return r;
}

// ---------------------------------------------------------------------------
// fp32 -> fp16 convert pre-pass
// ---------------------------------------------------------------------------
__global__ __launch_bounds__(256) void cvt16_kernel(const float* __restrict__ s,
                                                    __half* __restrict__ d, int n4) {
    int i = blockIdx.x * blockDim.x + threadIdx.x;
    if (i >= n4) return;
    float4 v = ((const float4*)s)[i];
    uint2 p;
    p.x = pack_f16x2(v.x, v.y);
    p.y = pack_f16x2(v.z, v.w);
    ((uint2*)d)[i] = p;
}

// ---------------------------------------------------------------------------
// Single-pass fp16 HMMA GEMM, K-stage = 32, 4-STAGE cp.async pipeline.
// D[128x128] = A[128xK] * B[128xK]^T, fp32 accum.
// smem: 4 stages x 2 arrays x 128 x ROWPAD fp16 = 81,920 B.
// ---------------------------------------------------------------------------
#define GAS (128 * ROWPAD)
#define GSTAGE (2 * GAS)          /* elems per stage */
#define NSTAGE_G 32               /* K stages */

template <int EPI>
__global__ __launch_bounds__(256, 2) void mma_gemm(const __half* __restrict__ Ap,
                                                   const __half* __restrict__ Bp,
                                                   const float* __restrict__ bias,
                                                   float* __restrict__ out) {
    extern __shared__ __half dsm[];
    const uint32_t aD = smem_u32(dsm);

    const int tid = threadIdx.x;
    const int wid = tid >> 5;
    const int lane = tid & 31;
    const int warp_m = wid & 1;
    const int warp_n = wid >> 1;
    const int m0 = blockIdx.y * 128;
    const int n0 = blockIdx.x * 128;

    const __half* srcA = Ap + (size_t)m0 * KDIM;
    const __half* srcB = Bp + (size_t)n0 * KDIM;

    const int a_row_base = warp_m * 64 + (lane & 15);
    const int a_colsel = (lane >> 4) * 8;
    const int b_row_base = warp_n * 32 + ((lane >> 4) & 1) * 8 + (lane & 7);
    const int b_colsel = ((lane >> 3) & 1) * 8;

    float acc[4][4][4];
#pragma unroll
    for (int mi = 0; mi < 4; mi++)
#pragma unroll
        for (int ni = 0; ni < 4; ni++)
#pragma unroll
            for (int e = 0; e < 4; e++) acc[mi][ni][e] = 0.0f;

    // Stage: 128 rows x 32 fp16 per array = 4 x 16B segs/row = 512 segs/array.
    // 1024 segs total; 4 cp16 per thread.
    auto issue = [&](int s) {
        const int k0 = s * 32;
        const uint32_t sb = aD + (uint32_t)(s & 3) * (GSTAGE * 2);
#pragma unroll
        for (int i = 0; i < 2; i++) {
            int idx = tid + i * 256;       // 0..511
            int r = idx >> 2;
            int sg = idx & 3;
            cp16(sb + (uint32_t)(r * ROWPAD + sg * 8) * 2,
                 srcA + (size_t)r * KDIM + k0 + sg * 8);
            cp16(sb + (uint32_t)(GAS + r * ROWPAD + sg * 8) * 2,
                 srcB + (size_t)r * KDIM + k0 + sg * 8);
        }
        CP_COMMIT();
    };

    issue(0); issue(1); issue(2);

    for (int s = 0; s < NSTAGE_G; s++) {
        cp_wait_taper(NSTAGE_G - 1 - s);
        __syncthreads();
        if (s + 3 < NSTAGE_G) issue(s + 3);

        const uint32_t sb = aD + (uint32_t)(s & 3) * (GSTAGE * 2);
        const uint32_t aA = sb;
        const uint32_t aB = sb + GAS * 2;

#pragma unroll
        for (int kk = 0; kk < 2; kk++) {
            const int acol = kk * 16 + a_colsel;
            const int bcol = kk * 16 + b_colsel;

            uint32_t fa[4][4];
            uint32_t fb[4][2];

#pragma unroll
            for (int mi = 0; mi < 4; mi++)
                ldm_x4(fa[mi], aA + ((a_row_base + mi * 16) * ROWPAD + acol) * 2);
#pragma unroll
            for (int ni2 = 0; ni2 < 2; ni2++)
                ldm_x4(&fb[ni2 * 2][0], aB + ((b_row_base + ni2 * 16) * ROWPAD + bcol) * 2);

#pragma unroll
            for (int mi = 0; mi < 4; mi++)
#pragma unroll
                for (int ni = 0; ni < 4; ni++) mma16816h(acc[mi][ni], fa[mi], fb[ni]);
        }
    }

    const int r0 = lane >> 2;
    const int c0 = (lane & 3) * 2;
#pragma unroll
    for (int mi = 0; mi < 4; mi++) {
#pragma unroll
        for (int half = 0; half < 2; half++) {
            const int m = m0 + warp_m * 64 + mi * 16 + r0 + half * 8;
            if (EPI == 0) {
                const int b = m >> 11;
                const int t = m & (TT - 1);
                const size_t mbase = ((size_t)b * HH) * TT;
#pragma unroll
                for (int ni = 0; ni < 4; ni++) {
#pragma unroll
                    for (int e = 0; e < 2; e++) {
                        int o = n0 + warp_n * 32 + ni * 8 + c0 + e;
                        float v = acc[mi][ni][half * 2 + e];
                        int d = o / 48;
                        int rem = o - d * 48;
                        int kq = rem >> 4;
                        int h = rem & 15;
                        __half* dst = (kq == 0) ? g_q16 : (kq == 1) ? g_k16 : g_v16;
                        size_t idx = ((mbase + (size_t)h * TT) + t) * DHD + d;
                        dst[idx] = __float2half(v);
                    }
                }
            } else {
#pragma unroll
                for (int ni = 0; ni < 4; ni++) {
#pragma unroll
                    for (int e = 0; e < 2; e++) {
                        int o = n0 + warp_n * 32 + ni * 8 + c0 + e;
                        out[(size_t)m * DIMD + o] = acc[mi][ni][half * 2 + e] + bias[o];
                    }
                }
            }
        }
    }
}

// ---------------------------------------------------------------------------
// fp16 single-pass HMMA flash attention, 4-STAGE cp.async pipeline.
// smem: 4 stages x (K,V) x 64 x APAD fp16 = 73,728 B. Q staged in stage 0.
// ---------------------------------------------------------------------------
#define ARR (64 * APAD)
#define ASTAGE (2 * ARR)
#define NSTAGE_A 32               /* key chunks */

__global__ __launch_bounds__(256, 2) void attn_mma_kernel() {
    extern __shared__ __half hsm[];
    const uint32_t aD = smem_u32(hsm);

    const int tid = threadIdx.x;
    const int w = tid >> 5;
    const int lane = tid & 31;
    const int bh = blockIdx.x >> 4;
    const int rb = blockIdx.x & 15;
    const int b = bh >> 4;
    const int h = bh & 15;
    const int row0 = rb * 128;

    const __half* Qp = g_q16 + (size_t)bh * TT * DHD;
    const __half* Kp = g_k16 + (size_t)bh * TT * DHD;
    const __half* Vp = g_v16 + (size_t)bh * TT * DHD;

    // ---- stage Q into stage-0 region, build fragments ----
#pragma unroll
    for (int i = 0; i < 4; i++) {
        int idx = tid + i * 256;
        int r = idx >> 3;
        int sg = idx & 7;
        *(uint4*)&hsm[r * APAD + sg * 8] =
            *(const uint4*)(Qp + (size_t)(row0 + r) * DHD + sg * 8);
    }
    __syncthreads();

    const uint32_t qrow = w * 16 + (lane & 15);
    const uint32_t qcol = (lane >> 4) * 8;
    uint32_t qf[4][4];
#pragma unroll
    for (int ks = 0; ks < 4; ks++)
        ldm_x4(qf[ks], aD + (qrow * APAD + ks * 16 + qcol) * 2);
    __syncthreads();   // Q reads done before cp.async overwrites stage 0

    const int ld_row = tid >> 2;
    const int ld_seg = tid & 3;

    auto issue = [&](int kt) {
        const size_t goff = (size_t)kt * 64 * DHD;
        const uint32_t sb = aD + (uint32_t)(kt & 3) * (ASTAGE * 2);
        const __half* srcs[2] = {Kp + goff, Vp + goff};
#pragma unroll
        for (int a = 0; a < 2; a++) {
#pragma unroll
            for (int i = 0; i < 2; i++) {
                int sg = ld_seg + i * 4;
                cp16(sb + (uint32_t)(a * ARR + ld_row * APAD + sg * 8) * 2,
                     srcs[a] + (size_t)ld_row * DHD + sg * 8);
            }
        }
        CP_COMMIT();
    };

    float accO[8][4];
#pragma unroll
    for (int nt = 0; nt < 8; nt++)
#pragma unroll
        for (int e = 0; e < 4; e++) accO[nt][e] = 0.0f;

    float M0 = -1e30f, M1 = -1e30f;
    float L0 = 0.0f, L1 = 0.0f;

    issue(0); issue(1); issue(2);

    const uint32_t k_rowl = ((lane >> 4) & 1) * 8 + (lane & 7);
    const uint32_t k_coll = ((lane >> 3) & 1) * 8;
    const uint32_t v_rowl = ((lane >> 3) & 1) * 8 + (lane & 7);
    const uint32_t v_coll = ((lane >> 4) & 1) * 8;

    for (int kt = 0; kt < NSTAGE_A; kt++) {
        cp_wait_taper(NSTAGE_A - 1 - kt);
        __syncthreads();
        if (kt + 3 < NSTAGE_A) issue(kt + 3);

        const uint32_t sb = aD + (uint32_t)(kt & 3) * (ASTAGE * 2);
        const uint32_t aK = sb;
        const uint32_t aV = sb + ARR * 2;

        // ---- S = Q K^T ----
        float accS[8][4];
#pragma unroll
        for (int nt = 0; nt < 8; nt++)
#pragma unroll
            for (int e = 0; e < 4; e++) accS[nt][e] = 0.0f;

#pragma unroll
        for (int ks = 0; ks < 4; ks++) {
#pragma unroll
            for (int np = 0; np < 2; np++) {
                uint32_t kfa[4], kfb[4];
                const uint32_t offA = (((2 * np) * 16 + k_rowl) * APAD + ks * 16 + k_coll) * 2;
                const uint32_t offB = (((2 * np + 1) * 16 + k_rowl) * APAD + ks * 16 + k_coll) * 2;
                ldm_x4(kfa, aK + offA);
                ldm_x4(kfb, aK + offB);
                mma16816h(accS[4 * np + 0], qf[ks], &kfa[0]);
                mma16816h(accS[4 * np + 1], qf[ks], &kfa[2]);
                mma16816h(accS[4 * np + 2], qf[ks], &kfb[0]);
                mma16816h(accS[4 * np + 3], qf[ks], &kfb[2]);
            }
        }

        // ---- online softmax ----
        float vm0 = accS[0][0], vm1 = accS[0][2];
#pragma unroll
        for (int nt = 0; nt < 8; nt++) {
            vm0 = fmaxf(vm0, fmaxf(accS[nt][0], accS[nt][1]));
            vm1 = fmaxf(vm1, fmaxf(accS[nt][2], accS[nt][3]));
        }
        vm0 = fmaxf(vm0, __shfl_xor_sync(0xffffffffu, vm0, 1));
        vm0 = fmaxf(vm0, __shfl_xor_sync(0xffffffffu, vm0, 2));
        vm1 = fmaxf(vm1, __shfl_xor_sync(0xffffffffu, vm1, 1));
        vm1 = fmaxf(vm1, __shfl_xor_sync(0xffffffffu, vm1, 2));

        const float Mn0 = fmaxf(M0, vm0);
        const float Mn1 = fmaxf(M1, vm1);
        const float corr0 = fexp2((M0 - Mn0) * EXP_C);
        const float corr1 = fexp2((M1 - Mn1) * EXP_C);
        M0 = Mn0; M1 = Mn1;
        const float mc0 = M0 * EXP_C;
        const float mc1 = M1 * EXP_C;

        float sp0 = 0.0f, sp1 = 0.0f;
#pragma unroll
        for (int nt = 0; nt < 8; nt++) {
            accS[nt][0] = fexp2(fmaf(accS[nt][0], EXP_C, -mc0));
            accS[nt][1] = fexp2(fmaf(accS[nt][1], EXP_C, -mc0));
            accS[nt][2] = fexp2(fmaf(accS[nt][2], EXP_C, -mc1));
            accS[nt][3] = fexp2(fmaf(accS[nt][3], EXP_C, -mc1));
            sp0 += accS[nt][0] + accS[nt][1];
            sp1 += accS[nt][2] + accS[nt][3];
        }
        sp0 += __shfl_xor_sync(0xffffffffu, sp0, 1);
        sp0 += __shfl_xor_sync(0xffffffffu, sp0, 2);
        sp1 += __shfl_xor_sync(0xffffffffu, sp1, 1);
        sp1 += __shfl_xor_sync(0xffffffffu, sp1, 2);
        L0 = L0 * corr0 + sp0;
        L1 = L1 * corr1 + sp1;

#pragma unroll
        for (int nt = 0; nt < 8; nt++) {
            accO[nt][0] *= corr0; accO[nt][1] *= corr0;
            accO[nt][2] *= corr1; accO[nt][3] *= corr1;
        }

        // ---- O += P V ----
#pragma unroll
        for (int kc = 0; kc < 4; kc++) {
            uint32_t ph[4];
#pragma unroll
            for (int half = 0; half < 2; half++) {
                const int nt = 2 * kc + half;
                ph[half * 2 + 0] = pack_f16x2(accS[nt][0], accS[nt][1]);
                ph[half * 2 + 1] = pack_f16x2(accS[nt][2], accS[nt][3]);
            }
            const uint32_t vrow = kc * 16 + v_rowl;
#pragma unroll
            for (int np = 0; np < 2; np++) {
                uint32_t vfa[4], vfb[4];
                const uint32_t offA = (vrow * APAD + (2 * np) * 16 + v_coll) * 2;
                const uint32_t offB = (vrow * APAD + (2 * np + 1) * 16 + v_coll) * 2;
                ldm_x4_trans(vfa, aV + offA);
                ldm_x4_trans(vfb, aV + offB);
                mma16816h(accO[4 * np + 0], ph, &vfa[0]);
                mma16816h(accO[4 * np + 1], ph, &vfa[2]);
                mma16816h(accO[4 * np + 2], ph, &vfb[0]);
                mma16816h(accO[4 * np + 3], ph, &vfb[2]);
            }
        }
    }

    // ---- epilogue: normalize, write fp16 g_ao16 ----
    const float i0 = 1.0f / L0;
    const float i1 = 1.0f / L1;
    const int r = lane >> 2;
    const int c = (lane & 3) * 2;
    const int row = row0 + w * 16 + r;
    const size_t base0 = ((size_t)b * TT + row) * DIMD + h * DHD + c;
    const size_t base1 = base0 + 8 * DIMD;
#pragma unroll
    for (int nt = 0; nt < 8; nt++) {
        *(uint32_t*)(g_ao16 + base0 + nt * 8) =
            pack_f16x2(accO[nt][0] * i0, accO[nt][1] * i0);
        *(uint32_t*)(g_ao16 + base1 + nt * 8) =
            pack_f16x2(accO[nt][2] * i1, accO[nt][3] * i1);
    }
}

// ---------------------------------------------------------------------------
extern "C" void kernel_launch(void* const* d_in, const int* in_sizes, int n_in,
                              void* d_out, int out_size) {
    const float* x     = (const float*)d_in[0];
    const float* w_qkv = (const float*)d_in[1];
    const float* w_out = (const float*)d_in[2];
    const float* b_out = (const float*)d_in[3];
    float* y = (float*)d_out;

    void *p_x16, *p_wq16, *p_wo16, *p_ao16;
    cudaGetSymbolAddress(&p_x16, g_x16);
    cudaGetSymbolAddress(&p_wq16, g_wq16);
    cudaGetSymbolAddress(&p_wo16, g_wo16);
    cudaGetSymbolAddress(&p_ao16, g_ao16);

    const int GEMM_SMEM = 4 * GSTAGE * 2;      // 81,920 B
    const int ATTN_SMEM = 4 * ASTAGE * 2;      // 73,728 B
    cudaFuncSetAttribute(mma_gemm<0>, cudaFuncAttributeMaxDynamicSharedMemorySize, GEMM_SMEM);
    cudaFuncSetAttribute(mma_gemm<1>, cudaFuncAttributeMaxDynamicSharedMemorySize, GEMM_SMEM);
    cudaFuncSetAttribute(attn_mma_kernel, cudaFuncAttributeMaxDynamicSharedMemorySize, ATTN_SMEM);

    {
        int n4 = (BB * TT * DIMD) / 4;
        cvt16_kernel<<<(n4 + 255) / 256, 256>>>(x, (__half*)p_x16, n4);
    }
    {
        int n4 = (NQKV * DIMD) / 4;
        cvt16_kernel<<<(n4 + 255) / 256, 256>>>(w_qkv, (__half*)p_wq16, n4);
    }
    {
        int n4 = (DIMD * DIMD) / 4;
        cvt16_kernel<<<(n4 + 255) / 256, 256>>>(w_out, (__half*)p_wo16, n4);
    }

    // QKV projection: M=8192, N=3072
    {
        dim3 g(NQKV / 128, (BB * TT) / 128);
        mma_gemm<0><<<g, 256, GEMM_SMEM>>>((const __half*)p_x16, (const __half*)p_wq16,
                                           nullptr, nullptr);
    }

    attn_mma_kernel<<<BB * HH * (TT / 128), 256, ATTN_SMEM>>>();

    // Output projection: M=8192, N=1024 (+bias)
    {
        dim3 g(DIMD / 128, (BB * TT) / 128);
        mma_gemm<1><<<g, 256, GEMM_SMEM>>>((const __half*)p_ao16, (const __half*)p_wo16,
                                           b_out, y);
    }
}